// round 1
// baseline (speedup 1.0000x reference)
#include <cuda_runtime.h>

// Problem constants
#define Bsz 32
#define Ssz 512
#define Lsz 8
#define Hsz 1024
#define Dsz 64

// Scratch: per-token MLP logit E and value projection V
__device__ float g_E[Bsz * Ssz];
__device__ float g_V[Bsz * Ssz];

#define TM 64   // tokens per block
#define KC 16   // K chunk

// Kernel 1: per-token  E[b,t] = relu((h*tw)@W1 + b1)@W2 + b2,  V[b,t] = h@Ws
// GEMM tiling: block = 64 tokens x 64 outputs, 256 threads, 4x4 microtile.
__global__ __launch_bounds__(256) void token_mlp_kernel(
    const float* __restrict__ hidden,
    const float* __restrict__ tw,
    const float* __restrict__ W1,
    const float* __restrict__ b1,
    const float* __restrict__ W2,
    const float* __restrict__ b2,
    const float* __restrict__ Ws)
{
    __shared__ float Xs[KC][TM];    // x = h*tw, transposed [k][token]
    __shared__ float Wsm[KC][Dsz];  // W1 chunk [k][d]

    const int t  = threadIdx.x;
    const int tx = t & 15;   // output group: d in [tx*4, tx*4+4)
    const int ty = t >> 4;   // token group: tokens [ty*4, ty*4+4)
    const int lm = t >> 2;   // loader token 0..63
    const int lq = t & 3;    // loader quad 0..3 (16 floats of K per chunk)

    const int b    = blockIdx.x >> 3;          // 8 blocks per batch row (512/64)
    const int tok0 = (blockIdx.x & 7) * TM;

    const float* hbase = hidden + ((size_t)b * Ssz + tok0 + lm) * Hsz;

    float acc[4][4] = {};
    float vpart = 0.0f;

    for (int k0 = 0; k0 < Hsz; k0 += KC) {
        // --- load W1 chunk: thread (r=ty, qd=tx) loads row k0+r, 4 floats ---
        {
            float4 w4 = *(const float4*)(W1 + (size_t)(k0 + ty) * Dsz + tx * 4);
            *(float4*)(&Wsm[ty][tx * 4]) = w4;
        }
        // --- load hidden chunk, premultiply tw, accumulate V partial ---
        {
            float4 h4 = *(const float4*)(hbase + k0 + lq * 4);
            float4 t4 = *(const float4*)(tw + k0 + lq * 4);
            float4 s4 = *(const float4*)(Ws + k0 + lq * 4);
            vpart = fmaf(h4.x, s4.x, vpart);
            vpart = fmaf(h4.y, s4.y, vpart);
            vpart = fmaf(h4.z, s4.z, vpart);
            vpart = fmaf(h4.w, s4.w, vpart);
            Xs[lq * 4 + 0][lm] = h4.x * t4.x;
            Xs[lq * 4 + 1][lm] = h4.y * t4.y;
            Xs[lq * 4 + 2][lm] = h4.z * t4.z;
            Xs[lq * 4 + 3][lm] = h4.w * t4.w;
        }
        __syncthreads();

        #pragma unroll
        for (int k = 0; k < KC; k++) {
            float4 xv = *(const float4*)(&Xs[k][ty * 4]);
            float4 wv = *(const float4*)(&Wsm[k][tx * 4]);
            acc[0][0] = fmaf(xv.x, wv.x, acc[0][0]);
            acc[0][1] = fmaf(xv.x, wv.y, acc[0][1]);
            acc[0][2] = fmaf(xv.x, wv.z, acc[0][2]);
            acc[0][3] = fmaf(xv.x, wv.w, acc[0][3]);
            acc[1][0] = fmaf(xv.y, wv.x, acc[1][0]);
            acc[1][1] = fmaf(xv.y, wv.y, acc[1][1]);
            acc[1][2] = fmaf(xv.y, wv.z, acc[1][2]);
            acc[1][3] = fmaf(xv.y, wv.w, acc[1][3]);
            acc[2][0] = fmaf(xv.z, wv.x, acc[2][0]);
            acc[2][1] = fmaf(xv.z, wv.y, acc[2][1]);
            acc[2][2] = fmaf(xv.z, wv.z, acc[2][2]);
            acc[2][3] = fmaf(xv.z, wv.w, acc[2][3]);
            acc[3][0] = fmaf(xv.w, wv.x, acc[3][0]);
            acc[3][1] = fmaf(xv.w, wv.y, acc[3][1]);
            acc[3][2] = fmaf(xv.w, wv.z, acc[3][2]);
            acc[3][3] = fmaf(xv.w, wv.w, acc[3][3]);
        }
        __syncthreads();
    }

    // --- V: reduce groups of 4 consecutive threads (same loader token) ---
    vpart += __shfl_xor_sync(0xffffffffu, vpart, 1, 4);
    vpart += __shfl_xor_sync(0xffffffffu, vpart, 2, 4);
    if (lq == 0) g_V[(size_t)b * Ssz + tok0 + lm] = vpart;

    // --- E: relu + W2 dot; reduce across the 16 tx lanes per token ---
    float4 b1v = *(const float4*)(b1 + tx * 4);
    float4 w2v = *(const float4*)(W2 + tx * 4);
    float b2v = b2[0];
    #pragma unroll
    for (int i = 0; i < 4; i++) {
        float pe = 0.0f;
        pe = fmaf(fmaxf(acc[i][0] + b1v.x, 0.0f), w2v.x, pe);
        pe = fmaf(fmaxf(acc[i][1] + b1v.y, 0.0f), w2v.y, pe);
        pe = fmaf(fmaxf(acc[i][2] + b1v.z, 0.0f), w2v.z, pe);
        pe = fmaf(fmaxf(acc[i][3] + b1v.w, 0.0f), w2v.w, pe);
        pe += __shfl_xor_sync(0xffffffffu, pe, 1, 16);
        pe += __shfl_xor_sync(0xffffffffu, pe, 2, 16);
        pe += __shfl_xor_sync(0xffffffffu, pe, 4, 16);
        pe += __shfl_xor_sync(0xffffffffu, pe, 8, 16);
        if (tx == 0) g_E[(size_t)b * Ssz + tok0 + ty * 4 + i] = pe + b2v;
    }
}

// Kernel 2: spans. One thread per (b,s). Online softmax over j<=l (valid only).
__global__ __launch_bounds__(256) void span_kernel(
    const int* __restrict__ seqlen,
    const float* __restrict__ bs,
    float* __restrict__ out)
{
    int idx = blockIdx.x * blockDim.x + threadIdx.x; // b*S + s
    if (idx >= Bsz * Ssz) return;
    int b = idx >> 9;
    int s = idx & (Ssz - 1);
    int len = seqlen[b];

    float ev[Lsz], vv[Lsz];
    #pragma unroll
    for (int j = 0; j < Lsz; j++) {
        int p = min(s + j, Ssz - 1);
        ev[j] = g_E[(b << 9) + p];
        vv[j] = g_V[(b << 9) + p];
    }

    const bool span_valid = (s < len);
    const float bsv = bs[0];

    float M = -1e30f, sum = 0.0f, wsum = 0.0f;
    #pragma unroll
    for (int l = 0; l < Lsz; l++) {
        if (s + l < len) {
            float e = ev[l];
            float newM = fmaxf(M, e);
            float scale = expf(M - newM);   // 0 on first valid elem (M=-1e30)
            float p = expf(e - newM);
            sum  = sum  * scale + p;
            wsum = wsum * scale + p * vv[l];
            M = newM;
        }
        float score = (sum > 0.0f) ? (wsum / sum + bsv) : bsv;
        out[(size_t)idx * Lsz + l] = span_valid ? score : 0.0f;
    }
}

extern "C" void kernel_launch(void* const* d_in, const int* in_sizes, int n_in,
                              void* d_out, int out_size)
{
    const float* hidden = (const float*)d_in[0];
    const int*   seqlen = (const int*)  d_in[1];
    const float* tw     = (const float*)d_in[2];
    const float* W1     = (const float*)d_in[3];
    const float* b1     = (const float*)d_in[4];
    const float* W2     = (const float*)d_in[5];
    const float* b2     = (const float*)d_in[6];
    const float* Ws     = (const float*)d_in[7];
    const float* bs     = (const float*)d_in[8];
    float* out = (float*)d_out;

    token_mlp_kernel<<<(Bsz * Ssz) / TM, 256>>>(hidden, tw, W1, b1, W2, b2, Ws);
    span_kernel<<<(Bsz * Ssz) / 256, 256>>>(seqlen, bs, out);
}